// round 1
// baseline (speedup 1.0000x reference)
#include <cuda_runtime.h>
#include <cstdint>

#define NMAX 100000
#define EMAX 800000
#define H    128
#define HH   64
#define TM   64
#define XSS  132   // H + 4 pad (floats)
#define HSS  68    // HH + 4 pad

// Scratch (static device arrays: allowed; no runtime allocation)
__device__ float g_invfeat[(size_t)NMAX * H];
__device__ float g_nsum[(size_t)NMAX * H];
__device__ float g_res[(size_t)NMAX * H];
__device__ int   g_deg[NMAX];

__device__ __forceinline__ float lrelu(float x) { return x >= 0.f ? x : 0.01f * x; }

// ---------------------------------------------------------------------------
__global__ void zero_kernel(int n)
{
    int i = blockIdx.x * blockDim.x + threadIdx.x;
    if (i < n * (H / 4))
        reinterpret_cast<float4*>(g_nsum)[i] = make_float4(0.f, 0.f, 0.f, 0.f);
    if (i < n) g_deg[i] = 0;
}

// ---------------------------------------------------------------------------
// One warp per edge: gather 128 floats from (r ? inv_feat : feat)[src], vector
// float atomics into nsum[dst]. Tables total 102MB -> mostly L2-resident.
__global__ __launch_bounds__(256) void scatter_kernel(
    const float* __restrict__ feat,
    const int* __restrict__ src, const int* __restrict__ dst,
    const int* __restrict__ r, int nedges)
{
    int g = blockIdx.x * blockDim.x + threadIdx.x;
    int e = g >> 5;
    if (e >= nedges) return;
    int lane = g & 31;

    int s  = src[e];
    int d  = dst[e];
    const float* tab = r[e] ? g_invfeat : feat;

    float4 v = *reinterpret_cast<const float4*>(tab + (size_t)s * H + lane * 4);
    float* p = g_nsum + (size_t)d * H + lane * 4;
    asm volatile("red.global.add.v4.f32 [%0], {%1, %2, %3, %4};"
                 :: "l"(p), "f"(v.x), "f"(v.y), "f"(v.z), "f"(v.w)
                 : "memory");
    if (lane == 0) atomicAdd(&g_deg[d], 1);
}

// ---------------------------------------------------------------------------
// Fused 3-layer MLP:  out = L3( lrelu(L2( lrelu(L1(x)) )) )
//  - optional deg: x-row scaled by 1/max(deg,1) at load (mean aggregation)
//  - optional sel/fb: rows with sel==0 get fb row copied instead of MLP result
// Block = 256 threads (16x16 thread grid), TM=64 rows/tile, persistent blocks.
// Weights staged transposed (k-major) in smem -> conflict-free float4 b-loads.
__global__ __launch_bounds__(256) void mlp3_kernel(
    const float* __restrict__ in, float* __restrict__ out,
    const float* __restrict__ w1, const float* __restrict__ b1,
    const float* __restrict__ w2, const float* __restrict__ b2,
    const float* __restrict__ w3, const float* __restrict__ b3,
    const int* __restrict__ deg,
    const int* __restrict__ sel, const float* __restrict__ fb,
    int nrows)
{
    extern __shared__ float sm[];
    float* xs  = sm;                    // TM * XSS
    float* h1  = xs  + TM * XSS;        // TM * HSS
    float* h2  = h1  + TM * HSS;        // TM * HSS
    float* w1t = h2  + TM * HSS;        // [H][HH]  k-major
    float* w2t = w1t + H * HH;          // [HH][HH] k-major
    float* w3t = w2t + HH * HH;         // [HH][H]  k-major
    float* b1s = w3t + HH * H;          // HH
    float* b2s = b1s + HH;              // HH
    float* b3s = b2s + HH;              // H

    const int tid = threadIdx.x;

    // Stage weights transposed: w[o][i] -> wt[i][o]
    for (int idx = tid; idx < H * HH; idx += 256) {       // w1 [HH][H]
        int i = idx / HH, o = idx % HH;
        w1t[idx] = w1[o * H + i];
    }
    for (int idx = tid; idx < HH * HH; idx += 256) {      // w2 [HH][HH]
        int i = idx / HH, o = idx % HH;
        w2t[idx] = w2[o * HH + i];
    }
    for (int idx = tid; idx < HH * H; idx += 256) {       // w3 [H][HH]
        int i = idx / H, o = idx % H;
        w3t[idx] = w3[o * HH + i];
    }
    if (tid < HH) { b1s[tid] = b1[tid]; b2s[tid] = b2[tid]; }
    if (tid < H)  { b3s[tid] = b3[tid]; }
    __syncthreads();

    const int ty = tid >> 4;   // 0..15 -> 4-row group
    const int tx = tid & 15;   // 0..15 -> 4-col group
    const int ntiles = (nrows + TM - 1) / TM;

    for (int tile = blockIdx.x; tile < ntiles; tile += gridDim.x) {
        const int row0 = tile * TM;

        // ---- load x tile (optionally scaled by 1/deg) ----
        for (int idx = tid; idx < TM * (H / 4); idx += 256) {
            int row = idx >> 5;            // /(H/4)
            int k4  = (idx & 31) << 2;
            int gr  = row0 + row;
            float4 v = make_float4(0.f, 0.f, 0.f, 0.f);
            if (gr < nrows) {
                v = *reinterpret_cast<const float4*>(in + (size_t)gr * H + k4);
                if (deg != nullptr) {
                    float s = 1.f / (float)max(deg[gr], 1);
                    v.x *= s; v.y *= s; v.z *= s; v.w *= s;
                }
            }
            *reinterpret_cast<float4*>(xs + row * XSS + k4) = v;
        }
        __syncthreads();

        // ---- layer 1: [TM,H] @ w1t -> h1 [TM,HH], lrelu ----
        {
            float acc[4][4];
            float4 bb = *reinterpret_cast<float4*>(b1s + 4 * tx);
            #pragma unroll
            for (int rr = 0; rr < 4; rr++) {
                acc[rr][0] = bb.x; acc[rr][1] = bb.y; acc[rr][2] = bb.z; acc[rr][3] = bb.w;
            }
            #pragma unroll 4
            for (int k = 0; k < H; k += 4) {
                float4 a[4];
                #pragma unroll
                for (int rr = 0; rr < 4; rr++)
                    a[rr] = *reinterpret_cast<float4*>(xs + (4 * ty + rr) * XSS + k);
                #pragma unroll
                for (int kk = 0; kk < 4; kk++) {
                    float4 b = *reinterpret_cast<float4*>(w1t + (k + kk) * HH + 4 * tx);
                    #pragma unroll
                    for (int rr = 0; rr < 4; rr++) {
                        float av = (&a[rr].x)[kk];
                        acc[rr][0] = fmaf(av, b.x, acc[rr][0]);
                        acc[rr][1] = fmaf(av, b.y, acc[rr][1]);
                        acc[rr][2] = fmaf(av, b.z, acc[rr][2]);
                        acc[rr][3] = fmaf(av, b.w, acc[rr][3]);
                    }
                }
            }
            #pragma unroll
            for (int rr = 0; rr < 4; rr++) {
                float4 v;
                v.x = lrelu(acc[rr][0]); v.y = lrelu(acc[rr][1]);
                v.z = lrelu(acc[rr][2]); v.w = lrelu(acc[rr][3]);
                *reinterpret_cast<float4*>(h1 + (4 * ty + rr) * HSS + 4 * tx) = v;
            }
        }
        __syncthreads();

        // ---- layer 2: h1 [TM,HH] @ w2t -> h2 [TM,HH], lrelu ----
        {
            float acc[4][4];
            float4 bb = *reinterpret_cast<float4*>(b2s + 4 * tx);
            #pragma unroll
            for (int rr = 0; rr < 4; rr++) {
                acc[rr][0] = bb.x; acc[rr][1] = bb.y; acc[rr][2] = bb.z; acc[rr][3] = bb.w;
            }
            #pragma unroll 4
            for (int k = 0; k < HH; k += 4) {
                float4 a[4];
                #pragma unroll
                for (int rr = 0; rr < 4; rr++)
                    a[rr] = *reinterpret_cast<float4*>(h1 + (4 * ty + rr) * HSS + k);
                #pragma unroll
                for (int kk = 0; kk < 4; kk++) {
                    float4 b = *reinterpret_cast<float4*>(w2t + (k + kk) * HH + 4 * tx);
                    #pragma unroll
                    for (int rr = 0; rr < 4; rr++) {
                        float av = (&a[rr].x)[kk];
                        acc[rr][0] = fmaf(av, b.x, acc[rr][0]);
                        acc[rr][1] = fmaf(av, b.y, acc[rr][1]);
                        acc[rr][2] = fmaf(av, b.z, acc[rr][2]);
                        acc[rr][3] = fmaf(av, b.w, acc[rr][3]);
                    }
                }
            }
            #pragma unroll
            for (int rr = 0; rr < 4; rr++) {
                float4 v;
                v.x = lrelu(acc[rr][0]); v.y = lrelu(acc[rr][1]);
                v.z = lrelu(acc[rr][2]); v.w = lrelu(acc[rr][3]);
                *reinterpret_cast<float4*>(h2 + (4 * ty + rr) * HSS + 4 * tx) = v;
            }
        }
        __syncthreads();

        // ---- layer 3: h2 [TM,HH] @ w3t -> out [TM,H]  (4x8 micro-tile) ----
        {
            float acc[4][8];
            float4 bb0 = *reinterpret_cast<float4*>(b3s + 4 * tx);
            float4 bb1 = *reinterpret_cast<float4*>(b3s + 64 + 4 * tx);
            #pragma unroll
            for (int rr = 0; rr < 4; rr++) {
                acc[rr][0] = bb0.x; acc[rr][1] = bb0.y; acc[rr][2] = bb0.z; acc[rr][3] = bb0.w;
                acc[rr][4] = bb1.x; acc[rr][5] = bb1.y; acc[rr][6] = bb1.z; acc[rr][7] = bb1.w;
            }
            #pragma unroll 4
            for (int k = 0; k < HH; k += 4) {
                float4 a[4];
                #pragma unroll
                for (int rr = 0; rr < 4; rr++)
                    a[rr] = *reinterpret_cast<float4*>(h2 + (4 * ty + rr) * HSS + k);
                #pragma unroll
                for (int kk = 0; kk < 4; kk++) {
                    float4 b0 = *reinterpret_cast<float4*>(w3t + (k + kk) * H + 4 * tx);
                    float4 b1v = *reinterpret_cast<float4*>(w3t + (k + kk) * H + 64 + 4 * tx);
                    #pragma unroll
                    for (int rr = 0; rr < 4; rr++) {
                        float av = (&a[rr].x)[kk];
                        acc[rr][0] = fmaf(av, b0.x, acc[rr][0]);
                        acc[rr][1] = fmaf(av, b0.y, acc[rr][1]);
                        acc[rr][2] = fmaf(av, b0.z, acc[rr][2]);
                        acc[rr][3] = fmaf(av, b0.w, acc[rr][3]);
                        acc[rr][4] = fmaf(av, b1v.x, acc[rr][4]);
                        acc[rr][5] = fmaf(av, b1v.y, acc[rr][5]);
                        acc[rr][6] = fmaf(av, b1v.z, acc[rr][6]);
                        acc[rr][7] = fmaf(av, b1v.w, acc[rr][7]);
                    }
                }
            }
            #pragma unroll
            for (int rr = 0; rr < 4; rr++) {
                int gr = row0 + 4 * ty + rr;
                if (gr >= nrows) continue;
                float4 v0 = make_float4(acc[rr][0], acc[rr][1], acc[rr][2], acc[rr][3]);
                float4 v1 = make_float4(acc[rr][4], acc[rr][5], acc[rr][6], acc[rr][7]);
                if (sel != nullptr && sel[gr] == 0) {
                    v0 = *reinterpret_cast<const float4*>(fb + (size_t)gr * H + 4 * tx);
                    v1 = *reinterpret_cast<const float4*>(fb + (size_t)gr * H + 64 + 4 * tx);
                }
                *reinterpret_cast<float4*>(out + (size_t)gr * H + 4 * tx)      = v0;
                *reinterpret_cast<float4*>(out + (size_t)gr * H + 64 + 4 * tx) = v1;
            }
        }
        __syncthreads();  // protect xs/h1/h2 for next tile
    }
}

// ---------------------------------------------------------------------------
static constexpr size_t MLP_SMEM =
    (TM * XSS + 2 * TM * HSS + H * HH + HH * HH + HH * H + 2 * HH + H) * sizeof(float);

extern "C" void kernel_launch(void* const* d_in, const int* in_sizes, int n_in,
                              void* d_out, int out_size)
{
    const float* feat   = (const float*)d_in[0];
    const int*   src    = (const int*)d_in[1];
    const int*   dst    = (const int*)d_in[2];
    const int*   r      = (const int*)d_in[3];
    const int*   inv    = (const int*)d_in[4];
    const float* inv_w1 = (const float*)d_in[5];
    const float* inv_b1 = (const float*)d_in[6];
    const float* inv_w2 = (const float*)d_in[7];
    const float* inv_b2 = (const float*)d_in[8];
    const float* inv_w3 = (const float*)d_in[9];
    const float* inv_b3 = (const float*)d_in[10];
    const float* and_w1 = (const float*)d_in[11];
    const float* and_b1 = (const float*)d_in[12];
    const float* and_w2 = (const float*)d_in[13];
    const float* and_b2 = (const float*)d_in[14];
    const float* and_w3 = (const float*)d_in[15];
    const float* and_b3 = (const float*)d_in[16];

    const int n = in_sizes[0] / H;
    const int e = in_sizes[1];

    float *invfeat, *nsum, *res;
    int* deg;
    cudaGetSymbolAddress((void**)&invfeat, g_invfeat);
    cudaGetSymbolAddress((void**)&nsum,    g_nsum);
    cudaGetSymbolAddress((void**)&res,     g_res);
    cudaGetSymbolAddress((void**)&deg,     g_deg);

    cudaFuncSetAttribute(mlp3_kernel,
                         cudaFuncAttributeMaxDynamicSharedMemorySize, (int)MLP_SMEM);

    // 1. zero accumulators
    int zgrid = (n * (H / 4) + 255) / 256;
    zero_kernel<<<zgrid, 256>>>(n);

    const int ntiles = (n + TM - 1) / TM;
    const int mgrid  = ntiles < 148 ? ntiles : 148;

    // 2. inv_feat = mlp3_inv(feat)   (per node, not per edge)
    mlp3_kernel<<<mgrid, 256, MLP_SMEM>>>(
        feat, invfeat, inv_w1, inv_b1, inv_w2, inv_b2, inv_w3, inv_b3,
        nullptr, nullptr, nullptr, n);

    // 3. edge gather + atomic scatter (mean numerator + degree)
    long long sthreads = (long long)e * 32;
    int sgrid = (int)((sthreads + 255) / 256);
    scatter_kernel<<<sgrid, 256>>>(feat, src, dst, r, e);

    // 4. res = mlp3_and(nsum / max(deg,1))
    mlp3_kernel<<<mgrid, 256, MLP_SMEM>>>(
        nsum, res, and_w1, and_b1, and_w2, and_b2, and_w3, and_b3,
        deg, nullptr, nullptr, n);

    // 5. out = inv ? mlp3_inv(res) : res
    mlp3_kernel<<<mgrid, 256, MLP_SMEM>>>(
        res, (float*)d_out, inv_w1, inv_b1, inv_w2, inv_b2, inv_w3, inv_b3,
        nullptr, inv, res, n);
}

// round 3
// speedup vs baseline: 1.3813x; 1.3813x over previous
#include <cuda_runtime.h>
#include <cuda_bf16.h>
#include <cstdint>

#define H    128
#define HH   64
#define NMAX 100000
#define TM   128

// ---------------------------------------------------------------------------
__device__ float g_invfeat[(size_t)NMAX * H];
__device__ float g_nsum[(size_t)NMAX * H];
__device__ float g_res[(size_t)NMAX * H];
__device__ int   g_deg[NMAX];

__device__ __forceinline__ float lrelu(float x) { return x >= 0.f ? x : 0.01f * x; }

// ---------------------------------------------------------------------------
// smem byte layout (single CTA plan, ~193KB)
#define XSB 272      // x plane row stride: (128+8) bf16
#define HSB 144      // h / w2 / w3 row stride: (64+8) bf16
#define OW1H 0
#define OW1L 17408
#define OW2H 34816
#define OW2L 44032
#define OW3H 53248
#define OW3L 71680
#define OXH  90112
#define OXL  124928
#define OHH  159744
#define OHL  178176
#define OB1  196608
#define OB2  196864
#define OB3  197120
#define SMEM_BYTES 197632

__device__ __forceinline__ uint32_t smem_u32(const void* p) {
    uint32_t a;
    asm("{ .reg .u64 t; cvta.to.shared.u64 t, %1; cvt.u32.u64 %0, t; }" : "=r"(a) : "l"(p));
    return a;
}

__device__ __forceinline__ void ldm_x4(uint32_t addr, uint32_t r[4]) {
    asm volatile("ldmatrix.sync.aligned.m8n8.x4.shared.b16 {%0,%1,%2,%3}, [%4];"
                 : "=r"(r[0]), "=r"(r[1]), "=r"(r[2]), "=r"(r[3]) : "r"(addr));
}

__device__ __forceinline__ void mma_bf16(float c[4], const uint32_t a[4],
                                         uint32_t b0, uint32_t b1) {
    asm volatile("mma.sync.aligned.m16n8k16.row.col.f32.bf16.bf16.f32 "
                 "{%0,%1,%2,%3}, {%4,%5,%6,%7}, {%8,%9}, {%0,%1,%2,%3};"
                 : "+f"(c[0]), "+f"(c[1]), "+f"(c[2]), "+f"(c[3])
                 : "r"(a[0]), "r"(a[1]), "r"(a[2]), "r"(a[3]), "r"(b0), "r"(b1));
}

// split pair (x=low col, y=high col) into bf16x2 hi and lo words
__device__ __forceinline__ void split2(float x, float y, uint32_t& hi, uint32_t& lo) {
    __nv_bfloat162 h = __floats2bfloat162_rn(x, y);
    float rx = x - __bfloat162float(h.x);
    float ry = y - __bfloat162float(h.y);
    __nv_bfloat162 l = __floats2bfloat162_rn(rx, ry);
    hi = *reinterpret_cast<uint32_t*>(&h);
    lo = *reinterpret_cast<uint32_t*>(&l);
}

// ---------------------------------------------------------------------------
__global__ void zero_kernel(int n) {
    int i = blockIdx.x * blockDim.x + threadIdx.x;
    if (i < n * (H / 4))
        reinterpret_cast<float4*>(g_nsum)[i] = make_float4(0.f, 0.f, 0.f, 0.f);
    if (i < n) g_deg[i] = 0;
}

__global__ __launch_bounds__(256) void scatter_kernel(
    const float* __restrict__ feat,
    const int* __restrict__ src, const int* __restrict__ dst,
    const int* __restrict__ r, int nedges) {
    int g = blockIdx.x * blockDim.x + threadIdx.x;
    int e = g >> 5;
    if (e >= nedges) return;
    int lane = g & 31;
    int s = src[e], d = dst[e];
    const float* tab = r[e] ? g_invfeat : feat;
    float4 v = *reinterpret_cast<const float4*>(tab + (size_t)s * H + lane * 4);
    float* p = g_nsum + (size_t)d * H + lane * 4;
    asm volatile("red.global.add.v4.f32 [%0], {%1, %2, %3, %4};"
                 :: "l"(p), "f"(v.x), "f"(v.y), "f"(v.z), "f"(v.w) : "memory");
    if (lane == 0) atomicAdd(&g_deg[d], 1);
}

// ---------------------------------------------------------------------------
// Fused 3-layer MLP on mma.sync bf16 with 2-way split, 3-term products.
// 8 warps x 16 rows each; activations warp-private -> no block syncs in loop.
__global__ __launch_bounds__(256, 1) void mlp3_mma(
    const float* __restrict__ in, float* __restrict__ out,
    const float* __restrict__ w1, const float* __restrict__ b1,
    const float* __restrict__ w2, const float* __restrict__ b2,
    const float* __restrict__ w3, const float* __restrict__ b3,
    const int* __restrict__ deg,
    const int* __restrict__ sel, const float* __restrict__ fb,
    int nrows) {
    extern __shared__ char wp[];
    const uint32_t sb = smem_u32(wp);

    const int tid  = threadIdx.x;
    const int wid  = tid >> 5;
    const int lane = tid & 31;

    // ---- stage weights bf16 hi/lo, [n][k] row-major padded ----
    for (int idx = tid; idx < HH * H; idx += 256) {      // w1 [64][128]
        int n = idx >> 7, k = idx & 127;
        float v = w1[idx];
        __nv_bfloat16 h = __float2bfloat16_rn(v);
        __nv_bfloat16 l = __float2bfloat16_rn(v - __bfloat162float(h));
        *(__nv_bfloat16*)(wp + OW1H + n * XSB + k * 2) = h;
        *(__nv_bfloat16*)(wp + OW1L + n * XSB + k * 2) = l;
    }
    for (int idx = tid; idx < HH * HH; idx += 256) {     // w2 [64][64]
        int n = idx >> 6, k = idx & 63;
        float v = w2[idx];
        __nv_bfloat16 h = __float2bfloat16_rn(v);
        __nv_bfloat16 l = __float2bfloat16_rn(v - __bfloat162float(h));
        *(__nv_bfloat16*)(wp + OW2H + n * HSB + k * 2) = h;
        *(__nv_bfloat16*)(wp + OW2L + n * HSB + k * 2) = l;
    }
    for (int idx = tid; idx < H * HH; idx += 256) {      // w3 [128][64]
        int n = idx >> 6, k = idx & 63;
        float v = w3[idx];
        __nv_bfloat16 h = __float2bfloat16_rn(v);
        __nv_bfloat16 l = __float2bfloat16_rn(v - __bfloat162float(h));
        *(__nv_bfloat16*)(wp + OW3H + n * HSB + k * 2) = h;
        *(__nv_bfloat16*)(wp + OW3L + n * HSB + k * 2) = l;
    }
    if (tid < HH) {
        ((float*)(wp + OB1))[tid] = b1[tid];
        ((float*)(wp + OB2))[tid] = b2[tid];
    }
    if (tid < H) ((float*)(wp + OB3))[tid] = b3[tid];
    __syncthreads();

    const float* b1s = (const float*)(wp + OB1);
    const float* b2s = (const float*)(wp + OB2);
    const float* b3s = (const float*)(wp + OB3);

    const int m0 = wid * 16;
    const int g  = lane >> 2;        // 0..7
    const int t  = lane & 3;         // 0..3

    // ldmatrix lane-address row/col selectors
    const int a_row = m0 + (lane & 15);
    const int a_kof = (lane >> 4) * 16;                       // bytes (8 elems)
    const int b_row = (lane & 7) + ((lane >> 4) << 3);
    const int b_kof = ((lane >> 3) & 1) * 16;                 // bytes

    // A-frag base addresses
    const uint32_t axh = sb + OXH + a_row * XSB + a_kof;
    const uint32_t axl = sb + OXL + a_row * XSB + a_kof;
    const uint32_t ahh = sb + OHH + a_row * HSB + a_kof;
    const uint32_t ahl = sb + OHL + a_row * HSB + a_kof;
    // B-frag base addresses
    const uint32_t bw1h = sb + OW1H + b_row * XSB + b_kof;
    const uint32_t bw1l = sb + OW1L + b_row * XSB + b_kof;
    const uint32_t bw2h = sb + OW2H + b_row * HSB + b_kof;
    const uint32_t bw2l = sb + OW2L + b_row * HSB + b_kof;
    const uint32_t bw3h = sb + OW3H + b_row * HSB + b_kof;
    const uint32_t bw3l = sb + OW3L + b_row * HSB + b_kof;

    const int ntiles = (nrows + TM - 1) / TM;

    for (int tile = blockIdx.x; tile < ntiles; tile += gridDim.x) {
        const int row0 = tile * TM;

        // ---- stage own 16 rows of x (split bf16 hi/lo) ----
        #pragma unroll 4
        for (int j = 0; j < 16; j++) {
            int grow = row0 + m0 + j;
            float4 v = make_float4(0.f, 0.f, 0.f, 0.f);
            if (grow < nrows) {
                v = *reinterpret_cast<const float4*>(in + (size_t)grow * H + lane * 4);
                if (deg != nullptr) {
                    float s = 1.f / (float)max(deg[grow], 1);
                    v.x *= s; v.y *= s; v.z *= s; v.w *= s;
                }
            }
            uint32_t h0, l0, h1, l1;
            split2(v.x, v.y, h0, l0);
            split2(v.z, v.w, h1, l1);
            uint32_t off = (m0 + j) * XSB + lane * 8;
            *(uint2*)(wp + OXH + off) = make_uint2(h0, h1);
            *(uint2*)(wp + OXL + off) = make_uint2(l0, l1);
        }
        __syncwarp();

        // ================= layer 1: K=128, N=64 =================
        {
            float acc[8][4] = {};
            #pragma unroll
            for (int kt = 0; kt < 8; kt++) {
                uint32_t ah[4], al[4];
                ldm_x4(axh + kt * 32, ah);
                ldm_x4(axl + kt * 32, al);
                #pragma unroll
                for (int np = 0; np < 4; np++) {
                    uint32_t bh[4], bl[4];
                    ldm_x4(bw1h + np * 16 * XSB + kt * 32, bh);
                    ldm_x4(bw1l + np * 16 * XSB + kt * 32, bl);
                    mma_bf16(acc[2*np],   ah, bh[0], bh[1]);
                    mma_bf16(acc[2*np+1], ah, bh[2], bh[3]);
                    mma_bf16(acc[2*np],   al, bh[0], bh[1]);
                    mma_bf16(acc[2*np+1], al, bh[2], bh[3]);
                    mma_bf16(acc[2*np],   ah, bl[0], bl[1]);
                    mma_bf16(acc[2*np+1], ah, bl[2], bl[3]);
                }
            }
            // epilogue -> h planes
            #pragma unroll
            for (int nt = 0; nt < 8; nt++) {
                int col = nt * 8 + 2 * t;
                float bx = b1s[col], by = b1s[col + 1];
                uint32_t hi, lo;
                split2(lrelu(acc[nt][0] + bx), lrelu(acc[nt][1] + by), hi, lo);
                uint32_t off = (m0 + g) * HSB + col * 2;
                *(uint32_t*)(wp + OHH + off) = hi;
                *(uint32_t*)(wp + OHL + off) = lo;
                split2(lrelu(acc[nt][2] + bx), lrelu(acc[nt][3] + by), hi, lo);
                off = (m0 + g + 8) * HSB + col * 2;
                *(uint32_t*)(wp + OHH + off) = hi;
                *(uint32_t*)(wp + OHL + off) = lo;
            }
        }
        __syncwarp();

        // ================= layer 2: K=64, N=64 =================
        {
            float acc[8][4] = {};
            #pragma unroll
            for (int kt = 0; kt < 4; kt++) {
                uint32_t ah[4], al[4];
                ldm_x4(ahh + kt * 32, ah);
                ldm_x4(ahl + kt * 32, al);
                #pragma unroll
                for (int np = 0; np < 4; np++) {
                    uint32_t bh[4], bl[4];
                    ldm_x4(bw2h + np * 16 * HSB + kt * 32, bh);
                    ldm_x4(bw2l + np * 16 * HSB + kt * 32, bl);
                    mma_bf16(acc[2*np],   ah, bh[0], bh[1]);
                    mma_bf16(acc[2*np+1], ah, bh[2], bh[3]);
                    mma_bf16(acc[2*np],   al, bh[0], bh[1]);
                    mma_bf16(acc[2*np+1], al, bh[2], bh[3]);
                    mma_bf16(acc[2*np],   ah, bl[0], bl[1]);
                    mma_bf16(acc[2*np+1], ah, bl[2], bl[3]);
                }
            }
            __syncwarp();  // all lanes done reading h before overwrite
            #pragma unroll
            for (int nt = 0; nt < 8; nt++) {
                int col = nt * 8 + 2 * t;
                float bx = b2s[col], by = b2s[col + 1];
                uint32_t hi, lo;
                split2(lrelu(acc[nt][0] + bx), lrelu(acc[nt][1] + by), hi, lo);
                uint32_t off = (m0 + g) * HSB + col * 2;
                *(uint32_t*)(wp + OHH + off) = hi;
                *(uint32_t*)(wp + OHL + off) = lo;
                split2(lrelu(acc[nt][2] + bx), lrelu(acc[nt][3] + by), hi, lo);
                off = (m0 + g + 8) * HSB + col * 2;
                *(uint32_t*)(wp + OHH + off) = hi;
                *(uint32_t*)(wp + OHL + off) = lo;
            }
        }
        __syncwarp();

        // ================= layer 3: K=64, N=128 (two halves) =================
        const int growg  = row0 + m0 + g;
        const int growg8 = growg + 8;
        const bool fbg  = (sel != nullptr) && (growg  < nrows) && (sel[growg]  == 0);
        const bool fbg8 = (sel != nullptr) && (growg8 < nrows) && (sel[growg8] == 0);

        #pragma unroll
        for (int nh = 0; nh < 2; nh++) {
            float acc[8][4] = {};
            #pragma unroll
            for (int kt = 0; kt < 4; kt++) {
                uint32_t ah[4], al[4];
                ldm_x4(ahh + kt * 32, ah);
                ldm_x4(ahl + kt * 32, al);
                #pragma unroll
                for (int np = 0; np < 4; np++) {
                    uint32_t bh[4], bl[4];
                    uint32_t boff = (nh * 64 + np * 16) * HSB + kt * 32;
                    ldm_x4(bw3h + boff, bh);
                    ldm_x4(bw3l + boff, bl);
                    mma_bf16(acc[2*np],   ah, bh[0], bh[1]);
                    mma_bf16(acc[2*np+1], ah, bh[2], bh[3]);
                    mma_bf16(acc[2*np],   al, bh[0], bh[1]);
                    mma_bf16(acc[2*np+1], al, bh[2], bh[3]);
                    mma_bf16(acc[2*np],   ah, bl[0], bl[1]);
                    mma_bf16(acc[2*np+1], ah, bl[2], bl[3]);
                }
            }
            #pragma unroll
            for (int nt = 0; nt < 8; nt++) {
                int col = nh * 64 + nt * 8 + 2 * t;
                float bx = b3s[col], by = b3s[col + 1];
                if (growg < nrows) {
                    float2 v = make_float2(acc[nt][0] + bx, acc[nt][1] + by);
                    if (fbg) v = *reinterpret_cast<const float2*>(fb + (size_t)growg * H + col);
                    *reinterpret_cast<float2*>(out + (size_t)growg * H + col) = v;
                }
                if (growg8 < nrows) {
                    float2 v = make_float2(acc[nt][2] + bx, acc[nt][3] + by);
                    if (fbg8) v = *reinterpret_cast<const float2*>(fb + (size_t)growg8 * H + col);
                    *reinterpret_cast<float2*>(out + (size_t)growg8 * H + col) = v;
                }
            }
        }
        __syncwarp();
    }
}

// ---------------------------------------------------------------------------
extern "C" void kernel_launch(void* const* d_in, const int* in_sizes, int n_in,
                              void* d_out, int out_size) {
    const float* feat   = (const float*)d_in[0];
    const int*   src    = (const int*)d_in[1];
    const int*   dst    = (const int*)d_in[2];
    const int*   r      = (const int*)d_in[3];
    const int*   inv    = (const int*)d_in[4];
    const float* inv_w1 = (const float*)d_in[5];
    const float* inv_b1 = (const float*)d_in[6];
    const float* inv_w2 = (const float*)d_in[7];
    const float* inv_b2 = (const float*)d_in[8];
    const float* inv_w3 = (const float*)d_in[9];
    const float* inv_b3 = (const float*)d_in[10];
    const float* and_w1 = (const float*)d_in[11];
    const float* and_b1 = (const float*)d_in[12];
    const float* and_w2 = (const float*)d_in[13];
    const float* and_b2 = (const float*)d_in[14];
    const float* and_w3 = (const float*)d_in[15];
    const float* and_b3 = (const float*)d_in[16];

    const int n = in_sizes[0] / H;
    const int e = in_sizes[1];

    float *invfeat, *nsum, *res;
    int* deg;
    cudaGetSymbolAddress((void**)&invfeat, g_invfeat);
    cudaGetSymbolAddress((void**)&nsum,    g_nsum);
    cudaGetSymbolAddress((void**)&res,     g_res);
    cudaGetSymbolAddress((void**)&deg,     g_deg);

    cudaFuncSetAttribute(mlp3_mma, cudaFuncAttributeMaxDynamicSharedMemorySize, SMEM_BYTES);

    // 1. zero accumulators
    int zgrid = (n * (H / 4) + 255) / 256;
    zero_kernel<<<zgrid, 256>>>(n);

    const int ntiles = (n + TM - 1) / TM;
    const int mgrid  = ntiles < 148 ? ntiles : 148;

    // 2. inv_feat = mlp3_inv(feat)
    mlp3_mma<<<mgrid, 256, SMEM_BYTES>>>(
        feat, invfeat, inv_w1, inv_b1, inv_w2, inv_b2, inv_w3, inv_b3,
        nullptr, nullptr, nullptr, n);

    // 3. edge gather + atomic scatter
    long long sthreads = (long long)e * 32;
    int sgrid = (int)((sthreads + 255) / 256);
    scatter_kernel<<<sgrid, 256>>>(feat, src, dst, r, e);

    // 4. res = mlp3_and(nsum / max(deg,1))
    mlp3_mma<<<mgrid, 256, SMEM_BYTES>>>(
        nsum, res, and_w1, and_b1, and_w2, and_b2, and_w3, and_b3,
        deg, nullptr, nullptr, n);

    // 5. out = inv ? mlp3_inv(res) : res
    mlp3_mma<<<mgrid, 256, SMEM_BYTES>>>(
        res, (float*)d_out, inv_w1, inv_b1, inv_w2, inv_b2, inv_w3, inv_b3,
        nullptr, inv, res, n);
}

// round 6
// speedup vs baseline: 1.8277x; 1.3232x over previous
#include <cuda_runtime.h>
#include <cuda_bf16.h>
#include <cstdint>

#define H    128
#define HH   64
#define NMAX 100000
#define TM   128

// ---------------------------------------------------------------------------
__device__ float g_invfeat[(size_t)NMAX * H];
__device__ float g_nsum[(size_t)NMAX * H];
__device__ float g_res[(size_t)NMAX * H];
__device__ int   g_deg[NMAX];

__device__ __forceinline__ float lrelu(float x) { return x >= 0.f ? x : 0.01f * x; }

// ---------------------------------------------------------------------------
// smem layout: weights hi/lo planes + biases only (~91KB)
#define XSB 272      // w1 row stride: (128+8) bf16
#define HSB 144      // w2/w3 row stride: (64+8) bf16
#define OW1H 0
#define OW1L 17408
#define OW2H 34816
#define OW2L 44032
#define OW3H 53248
#define OW3L 71680
#define OB1  90112
#define OB2  90368
#define OB3  90624
#define SMEM_BYTES 91648

__device__ __forceinline__ uint32_t smem_u32(const void* p) {
    uint32_t a;
    asm("{ .reg .u64 t; cvta.to.shared.u64 t, %1; cvt.u32.u64 %0, t; }" : "=r"(a) : "l"(p));
    return a;
}

__device__ __forceinline__ void ldm_x4(uint32_t addr, uint32_t r[4]) {
    asm volatile("ldmatrix.sync.aligned.m8n8.x4.shared.b16 {%0,%1,%2,%3}, [%4];"
                 : "=r"(r[0]), "=r"(r[1]), "=r"(r[2]), "=r"(r[3]) : "r"(addr));
}

__device__ __forceinline__ void mma_bf16(float c[4], const uint32_t a[4],
                                         uint32_t b0, uint32_t b1) {
    asm volatile("mma.sync.aligned.m16n8k16.row.col.f32.bf16.bf16.f32 "
                 "{%0,%1,%2,%3}, {%4,%5,%6,%7}, {%8,%9}, {%0,%1,%2,%3};"
                 : "+f"(c[0]), "+f"(c[1]), "+f"(c[2]), "+f"(c[3])
                 : "r"(a[0]), "r"(a[1]), "r"(a[2]), "r"(a[3]), "r"(b0), "r"(b1));
}

// split pair (x=even col, y=odd col) into bf16x2 hi and lo words
__device__ __forceinline__ void split2(float x, float y, uint32_t& hi, uint32_t& lo) {
    __nv_bfloat162 h = __floats2bfloat162_rn(x, y);
    float rx = x - __bfloat162float(h.x);
    float ry = y - __bfloat162float(h.y);
    __nv_bfloat162 l = __floats2bfloat162_rn(rx, ry);
    hi = *reinterpret_cast<uint32_t*>(&h);
    lo = *reinterpret_cast<uint32_t*>(&l);
}

// term sweep: 8 distinct accumulators between same-acc reuse
__device__ __forceinline__ void sweep(float acc[8][4], const uint32_t a[4],
                                      const uint32_t b[4][4]) {
    #pragma unroll
    for (int np = 0; np < 4; np++) {
        mma_bf16(acc[2*np],   a, b[np][0], b[np][1]);
        mma_bf16(acc[2*np+1], a, b[np][2], b[np][3]);
    }
}

// C-frag (8 n-tiles) -> next layer A-frags (4 k-chunks), bias+lrelu+split in regs
__device__ __forceinline__ void epi_frag(const float a[8][4], const float* bs, int t,
                                         uint32_t fh[4][4], uint32_t fl[4][4]) {
    #pragma unroll
    for (int k = 0; k < 4; k++) {
        int ce = 16 * k + 2 * t, co = ce + 8;
        float be0 = bs[ce], be1 = bs[ce + 1], bo0 = bs[co], bo1 = bs[co + 1];
        split2(lrelu(a[2*k][0] + be0),   lrelu(a[2*k][1] + be1),   fh[k][0], fl[k][0]);
        split2(lrelu(a[2*k][2] + be0),   lrelu(a[2*k][3] + be1),   fh[k][1], fl[k][1]);
        split2(lrelu(a[2*k+1][0] + bo0), lrelu(a[2*k+1][1] + bo1), fh[k][2], fl[k][2]);
        split2(lrelu(a[2*k+1][2] + bo0), lrelu(a[2*k+1][3] + bo1), fh[k][3], fl[k][3]);
    }
}

// ---------------------------------------------------------------------------
__global__ void zero_kernel(int n) {
    int i = blockIdx.x * blockDim.x + threadIdx.x;
    if (i < n * (H / 4))
        reinterpret_cast<float4*>(g_nsum)[i] = make_float4(0.f, 0.f, 0.f, 0.f);
    if (i < n) g_deg[i] = 0;
}

__global__ __launch_bounds__(256) void scatter_kernel(
    const float* __restrict__ feat,
    const int* __restrict__ src, const int* __restrict__ dst,
    const int* __restrict__ r, int nedges) {
    int g = blockIdx.x * blockDim.x + threadIdx.x;
    int e = g >> 5;
    if (e >= nedges) return;
    int lane = g & 31;
    int s = src[e], d = dst[e];
    const float* tab = r[e] ? g_invfeat : feat;
    float4 v = *reinterpret_cast<const float4*>(tab + (size_t)s * H + lane * 4);
    float* p = g_nsum + (size_t)d * H + lane * 4;
    asm volatile("red.global.add.v4.f32 [%0], {%1, %2, %3, %4};"
                 :: "l"(p), "f"(v.x), "f"(v.y), "f"(v.z), "f"(v.w) : "memory");
    if (lane == 0) atomicAdd(&g_deg[d], 1);
}

// ---------------------------------------------------------------------------
// Fused 3-layer MLP: bf16 split mma.sync, activations fully register-resident.
__global__ __launch_bounds__(256, 1) void mlp3_mma(
    const float* __restrict__ in, float* __restrict__ out,
    const float* __restrict__ w1, const float* __restrict__ b1,
    const float* __restrict__ w2, const float* __restrict__ b2,
    const float* __restrict__ w3, const float* __restrict__ b3,
    const int* __restrict__ deg,
    const int* __restrict__ sel, const float* __restrict__ fb,
    int nrows) {
    extern __shared__ char wp[];
    const uint32_t sb = smem_u32(wp);

    const int tid  = threadIdx.x;
    const int wid  = tid >> 5;
    const int lane = tid & 31;

    // ---- stage weights bf16 hi/lo, [n][k] row-major padded ----
    for (int idx = tid; idx < HH * H; idx += 256) {      // w1 [64][128]
        int n = idx >> 7, k = idx & 127;
        float v = w1[idx];
        __nv_bfloat16 h = __float2bfloat16_rn(v);
        __nv_bfloat16 l = __float2bfloat16_rn(v - __bfloat162float(h));
        *(__nv_bfloat16*)(wp + OW1H + n * XSB + k * 2) = h;
        *(__nv_bfloat16*)(wp + OW1L + n * XSB + k * 2) = l;
    }
    for (int idx = tid; idx < HH * HH; idx += 256) {     // w2 [64][64]
        int n = idx >> 6, k = idx & 63;
        float v = w2[idx];
        __nv_bfloat16 h = __float2bfloat16_rn(v);
        __nv_bfloat16 l = __float2bfloat16_rn(v - __bfloat162float(h));
        *(__nv_bfloat16*)(wp + OW2H + n * HSB + k * 2) = h;
        *(__nv_bfloat16*)(wp + OW2L + n * HSB + k * 2) = l;
    }
    for (int idx = tid; idx < H * HH; idx += 256) {      // w3 [128][64]
        int n = idx >> 6, k = idx & 63;
        float v = w3[idx];
        __nv_bfloat16 h = __float2bfloat16_rn(v);
        __nv_bfloat16 l = __float2bfloat16_rn(v - __bfloat162float(h));
        *(__nv_bfloat16*)(wp + OW3H + n * HSB + k * 2) = h;
        *(__nv_bfloat16*)(wp + OW3L + n * HSB + k * 2) = l;
    }
    if (tid < HH) {
        ((float*)(wp + OB1))[tid] = b1[tid];
        ((float*)(wp + OB2))[tid] = b2[tid];
    }
    if (tid < H) ((float*)(wp + OB3))[tid] = b3[tid];
    __syncthreads();

    const float* b1s = (const float*)(wp + OB1);
    const float* b2s = (const float*)(wp + OB2);
    const float* b3s = (const float*)(wp + OB3);

    const int m0 = wid * 16;
    const int g  = lane >> 2;        // 0..7
    const int t  = lane & 3;         // 0..3

    // B-frag ldmatrix lane addressing
    const int b_row = (lane & 7) + ((lane >> 4) << 3);
    const int b_kof = ((lane >> 3) & 1) * 16;
    const uint32_t bw1h = sb + OW1H + b_row * XSB + b_kof;
    const uint32_t bw1l = sb + OW1L + b_row * XSB + b_kof;
    const uint32_t bw2h = sb + OW2H + b_row * HSB + b_kof;
    const uint32_t bw2l = sb + OW2L + b_row * HSB + b_kof;
    const uint32_t bw3h = sb + OW3H + b_row * HSB + b_kof;
    const uint32_t bw3l = sb + OW3L + b_row * HSB + b_kof;

    const int ntiles = (nrows + TM - 1) / TM;

    for (int tile = blockIdx.x; tile < ntiles; tile += gridDim.x) {
        const int row0  = tile * TM;
        const int rowg  = row0 + m0 + g;
        const int rowg8 = rowg + 8;
        const bool okg  = rowg  < nrows;
        const bool okg8 = rowg8 < nrows;

        float sg = 1.f, sg8 = 1.f;
        if (deg != nullptr) {
            if (okg)  sg  = 1.f / (float)max(deg[rowg],  1);
            if (okg8) sg8 = 1.f / (float)max(deg[rowg8], 1);
        }
        const float* rp  = in + (size_t)rowg  * H + 2 * t;
        const float* rp8 = in + (size_t)rowg8 * H + 2 * t;

        // ================= layer 1: K=128, N=64 =================
        float acc[8][4] = {};
        #pragma unroll
        for (int kt = 0; kt < 8; kt++) {
            // A frags direct from gmem (t-lanes cover one 32B sector)
            float2 p0 = okg  ? *(const float2*)(rp  + kt * 16)     : make_float2(0.f, 0.f);
            float2 p1 = okg8 ? *(const float2*)(rp8 + kt * 16)     : make_float2(0.f, 0.f);
            float2 p2 = okg  ? *(const float2*)(rp  + kt * 16 + 8) : make_float2(0.f, 0.f);
            float2 p3 = okg8 ? *(const float2*)(rp8 + kt * 16 + 8) : make_float2(0.f, 0.f);
            uint32_t ah[4], al[4];
            split2(p0.x * sg,  p0.y * sg,  ah[0], al[0]);
            split2(p1.x * sg8, p1.y * sg8, ah[1], al[1]);
            split2(p2.x * sg,  p2.y * sg,  ah[2], al[2]);
            split2(p3.x * sg8, p3.y * sg8, ah[3], al[3]);

            uint32_t bh[4][4], bl[4][4];
            #pragma unroll
            for (int np = 0; np < 4; np++) {
                ldm_x4(bw1h + np * 16 * XSB + kt * 32, bh[np]);
                ldm_x4(bw1l + np * 16 * XSB + kt * 32, bl[np]);
            }
            sweep(acc, ah, bh);
            sweep(acc, al, bh);
            sweep(acc, ah, bl);
        }

        // epi 1 -> layer-2 A frags (registers)
        uint32_t a2h[4][4], a2l[4][4];
        epi_frag(acc, b1s, t, a2h, a2l);

        // ================= layer 2: K=64, N=64 =================
        float acc2[8][4] = {};
        #pragma unroll
        for (int kt = 0; kt < 4; kt++) {
            uint32_t bh[4][4], bl[4][4];
            #pragma unroll
            for (int np = 0; np < 4; np++) {
                ldm_x4(bw2h + np * 16 * HSB + kt * 32, bh[np]);
                ldm_x4(bw2l + np * 16 * HSB + kt * 32, bl[np]);
            }
            sweep(acc2, a2h[kt], bh);
            sweep(acc2, a2l[kt], bh);
            sweep(acc2, a2h[kt], bl);
        }

        // epi 2 -> layer-3 A frags
        uint32_t a3h[4][4], a3l[4][4];
        epi_frag(acc2, b2s, t, a3h, a3l);

        // ================= layer 3: K=64, N=128 (two halves) =================
        const bool fbg  = (sel != nullptr) && okg  && (sel[rowg]  == 0);
        const bool fbg8 = (sel != nullptr) && okg8 && (sel[rowg8] == 0);

        #pragma unroll
        for (int nh = 0; nh < 2; nh++) {
            float acc3[8][4] = {};
            #pragma unroll
            for (int kt = 0; kt < 4; kt++) {
                uint32_t bh[4][4], bl[4][4];
                #pragma unroll
                for (int np = 0; np < 4; np++) {
                    uint32_t boff = (nh * 64 + np * 16) * HSB + kt * 32;
                    ldm_x4(bw3h + boff, bh[np]);
                    ldm_x4(bw3l + boff, bl[np]);
                }
                sweep(acc3, a3h[kt], bh);
                sweep(acc3, a3l[kt], bh);
                sweep(acc3, a3h[kt], bl);
            }
            #pragma unroll
            for (int nt = 0; nt < 8; nt++) {
                int col = nh * 64 + nt * 8 + 2 * t;
                float bx = b3s[col], by = b3s[col + 1];
                if (okg) {
                    float2 v = make_float2(acc3[nt][0] + bx, acc3[nt][1] + by);
                    if (fbg) v = *reinterpret_cast<const float2*>(fb + (size_t)rowg * H + col);
                    *reinterpret_cast<float2*>(out + (size_t)rowg * H + col) = v;
                }
                if (okg8) {
                    float2 v = make_float2(acc3[nt][2] + bx, acc3[nt][3] + by);
                    if (fbg8) v = *reinterpret_cast<const float2*>(fb + (size_t)rowg8 * H + col);
                    *reinterpret_cast<float2*>(out + (size_t)rowg8 * H + col) = v;
                }
            }
        }
    }
}

// ---------------------------------------------------------------------------
extern "C" void kernel_launch(void* const* d_in, const int* in_sizes, int n_in,
                              void* d_out, int out_size) {
    const float* feat   = (const float*)d_in[0];
    const int*   src    = (const int*)d_in[1];
    const int*   dst    = (const int*)d_in[2];
    const int*   r      = (const int*)d_in[3];
    const int*   inv    = (const int*)d_in[4];
    const float* inv_w1 = (const float*)d_in[5];
    const float* inv_b1 = (const float*)d_in[6];
    const float* inv_w2 = (const float*)d_in[7];
    const float* inv_b2 = (const float*)d_in[8];
    const float* inv_w3 = (const float*)d_in[9];
    const float* inv_b3 = (const float*)d_in[10];
    const float* and_w1 = (const float*)d_in[11];
    const float* and_b1 = (const float*)d_in[12];
    const float* and_w2 = (const float*)d_in[13];
    const float* and_b2 = (const float*)d_in[14];
    const float* and_w3 = (const float*)d_in[15];
    const float* and_b3 = (const float*)d_in[16];

    const int n = in_sizes[0] / H;
    const int e = in_sizes[1];

    float *invfeat, *nsum, *res;
    int* deg;
    cudaGetSymbolAddress((void**)&invfeat, g_invfeat);
    cudaGetSymbolAddress((void**)&nsum,    g_nsum);
    cudaGetSymbolAddress((void**)&res,     g_res);
    cudaGetSymbolAddress((void**)&deg,     g_deg);

    cudaFuncSetAttribute(mlp3_mma, cudaFuncAttributeMaxDynamicSharedMemorySize, SMEM_BYTES);

    // 1. zero accumulators
    int zgrid = (n * (H / 4) + 255) / 256;
    zero_kernel<<<zgrid, 256>>>(n);

    const int ntiles = (n + TM - 1) / TM;
    const int mgrid  = ntiles < 148 ? ntiles : 148;

    // 2. inv_feat = mlp3_inv(feat)
    mlp3_mma<<<mgrid, 256, SMEM_BYTES>>>(
        feat, invfeat, inv_w1, inv_b1, inv_w2, inv_b2, inv_w3, inv_b3,
        nullptr, nullptr, nullptr, n);

    // 3. edge gather + atomic scatter
    long long sthreads = (long long)e * 32;
    int sgrid = (int)((sthreads + 255) / 256);
    scatter_kernel<<<sgrid, 256>>>(feat, src, dst, r, e);

    // 4. res = mlp3_and(nsum / max(deg,1))
    mlp3_mma<<<mgrid, 256, SMEM_BYTES>>>(
        nsum, res, and_w1, and_b1, and_w2, and_b2, and_w3, and_b3,
        deg, nullptr, nullptr, n);

    // 5. out = inv ? mlp3_inv(res) : res
    mlp3_mma<<<mgrid, 256, SMEM_BYTES>>>(
        res, (float*)d_out, inv_w1, inv_b1, inv_w2, inv_b2, inv_w3, inv_b3,
        nullptr, inv, res, n);
}

// round 8
// speedup vs baseline: 1.9400x; 1.0614x over previous
#include <cuda_runtime.h>
#include <cuda_bf16.h>
#include <cstdint>

#define H    128
#define HH   64
#define NMAX 100000
#define TM   128

// ---------------------------------------------------------------------------
__device__ float g_invfeat[(size_t)NMAX * H];
__device__ float g_nsum[(size_t)NMAX * H];
__device__ float g_res[(size_t)NMAX * H];
__device__ int   g_deg[NMAX];
__device__ int   g_idx[NMAX];
__device__ int   g_cnt;

__device__ __forceinline__ float lrelu(float x) { return x >= 0.f ? x : 0.01f * x; }

// ---------------------------------------------------------------------------
// smem layout: weights hi/lo planes + biases only (~91KB)
#define XSB 272      // w1 row stride: (128+8) bf16
#define HSB 144      // w2/w3 row stride: (64+8) bf16
#define OW1H 0
#define OW1L 17408
#define OW2H 34816
#define OW2L 44032
#define OW3H 53248
#define OW3L 71680
#define OB1  90112
#define OB2  90368
#define OB3  90624
#define SMEM_BYTES 91648

__device__ __forceinline__ uint32_t smem_u32(const void* p) {
    uint32_t a;
    asm("{ .reg .u64 t; cvta.to.shared.u64 t, %1; cvt.u32.u64 %0, t; }" : "=r"(a) : "l"(p));
    return a;
}

__device__ __forceinline__ void ldm_x4(uint32_t addr, uint32_t r[4]) {
    asm volatile("ldmatrix.sync.aligned.m8n8.x4.shared.b16 {%0,%1,%2,%3}, [%4];"
                 : "=r"(r[0]), "=r"(r[1]), "=r"(r[2]), "=r"(r[3]) : "r"(addr));
}

__device__ __forceinline__ void mma_bf16(float c[4], const uint32_t a[4],
                                         uint32_t b0, uint32_t b1) {
    asm volatile("mma.sync.aligned.m16n8k16.row.col.f32.bf16.bf16.f32 "
                 "{%0,%1,%2,%3}, {%4,%5,%6,%7}, {%8,%9}, {%0,%1,%2,%3};"
                 : "+f"(c[0]), "+f"(c[1]), "+f"(c[2]), "+f"(c[3])
                 : "r"(a[0]), "r"(a[1]), "r"(a[2]), "r"(a[3]), "r"(b0), "r"(b1));
}

// split pair (x=even col, y=odd col) into bf16x2 hi and lo words
__device__ __forceinline__ void split2(float x, float y, uint32_t& hi, uint32_t& lo) {
    __nv_bfloat162 h = __floats2bfloat162_rn(x, y);
    float rx = x - __bfloat162float(h.x);
    float ry = y - __bfloat162float(h.y);
    __nv_bfloat162 l = __floats2bfloat162_rn(rx, ry);
    hi = *reinterpret_cast<uint32_t*>(&h);
    lo = *reinterpret_cast<uint32_t*>(&l);
}

// term sweep: 8 distinct accumulators between same-acc reuse
__device__ __forceinline__ void sweep(float acc[8][4], const uint32_t a[4],
                                      const uint32_t b[4][4]) {
    #pragma unroll
    for (int np = 0; np < 4; np++) {
        mma_bf16(acc[2*np],   a, b[np][0], b[np][1]);
        mma_bf16(acc[2*np+1], a, b[np][2], b[np][3]);
    }
}

// C-frag (8 n-tiles) -> next layer A-frags (4 k-chunks), bias+lrelu+split in regs
__device__ __forceinline__ void epi_frag(const float a[8][4], const float* bs, int t,
                                         uint32_t fh[4][4], uint32_t fl[4][4]) {
    #pragma unroll
    for (int k = 0; k < 4; k++) {
        int ce = 16 * k + 2 * t, co = ce + 8;
        float be0 = bs[ce], be1 = bs[ce + 1], bo0 = bs[co], bo1 = bs[co + 1];
        split2(lrelu(a[2*k][0] + be0),   lrelu(a[2*k][1] + be1),   fh[k][0], fl[k][0]);
        split2(lrelu(a[2*k][2] + be0),   lrelu(a[2*k][3] + be1),   fh[k][1], fl[k][1]);
        split2(lrelu(a[2*k+1][0] + bo0), lrelu(a[2*k+1][1] + bo1), fh[k][2], fl[k][2]);
        split2(lrelu(a[2*k+1][2] + bo0), lrelu(a[2*k+1][3] + bo1), fh[k][3], fl[k][3]);
    }
}

// ---------------------------------------------------------------------------
__global__ void zero_kernel(int n) {
    int i = blockIdx.x * blockDim.x + threadIdx.x;
    if (i < n * (H / 4))
        reinterpret_cast<float4*>(g_nsum)[i] = make_float4(0.f, 0.f, 0.f, 0.f);
    if (i < n) g_deg[i] = 0;
    if (i == 0) g_cnt = 0;
}

__global__ __launch_bounds__(256) void scatter_kernel(
    const float* __restrict__ feat,
    const int* __restrict__ src, const int* __restrict__ dst,
    const int* __restrict__ r, int nedges) {
    int g = blockIdx.x * blockDim.x + threadIdx.x;
    int e = g >> 5;
    if (e >= nedges) return;
    int lane = g & 31;
    int s = src[e], d = dst[e];
    const float* tab = r[e] ? g_invfeat : feat;
    float4 v = *reinterpret_cast<const float4*>(tab + (size_t)s * H + lane * 4);
    float* p = g_nsum + (size_t)d * H + lane * 4;
    asm volatile("red.global.add.v4.f32 [%0], {%1, %2, %3, %4};"
                 :: "l"(p), "f"(v.x), "f"(v.y), "f"(v.z), "f"(v.w) : "memory");
    if (lane == 0) atomicAdd(&g_deg[d], 1);
}

// ---------------------------------------------------------------------------
// warp per row: inv==1 rows -> append to index list; inv==0 rows -> copy res->out
__global__ __launch_bounds__(256) void compact_kernel(
    const int* __restrict__ inv, const float* __restrict__ res,
    float* __restrict__ out, int n) {
    int w    = (blockIdx.x * blockDim.x + threadIdx.x) >> 5;
    int lane = threadIdx.x & 31;
    int nw   = (gridDim.x * blockDim.x) >> 5;
    for (int row = w; row < n; row += nw) {
        if (inv[row] == 1) {
            if (lane == 0) {
                int p = atomicAdd(&g_cnt, 1);
                g_idx[p] = row;
            }
        } else {
            float4 v = reinterpret_cast<const float4*>(res + (size_t)row * H)[lane];
            reinterpret_cast<float4*>(out + (size_t)row * H)[lane] = v;
        }
    }
}

// ---------------------------------------------------------------------------
// Fused 3-layer MLP: bf16 split mma.sync, activations register-resident.
// rowidx/cnt_dev: optional row indirection (count read from device).
__global__ __launch_bounds__(256, 2) void mlp3_mma(
    const float* __restrict__ in, float* __restrict__ out,
    const float* __restrict__ w1, const float* __restrict__ b1,
    const float* __restrict__ w2, const float* __restrict__ b2,
    const float* __restrict__ w3, const float* __restrict__ b3,
    const int* __restrict__ deg,
    const int* __restrict__ rowidx, const int* __restrict__ cnt_dev,
    int nrows) {
    extern __shared__ char wp[];
    const uint32_t sb = smem_u32(wp);

    const int tid  = threadIdx.x;
    const int wid  = tid >> 5;
    const int lane = tid & 31;

    // ---- stage weights bf16 hi/lo, [n][k] row-major padded ----
    for (int idx = tid; idx < HH * H; idx += 256) {      // w1 [64][128]
        int n = idx >> 7, k = idx & 127;
        float v = w1[idx];
        __nv_bfloat16 h = __float2bfloat16_rn(v);
        __nv_bfloat16 l = __float2bfloat16_rn(v - __bfloat162float(h));
        *(__nv_bfloat16*)(wp + OW1H + n * XSB + k * 2) = h;
        *(__nv_bfloat16*)(wp + OW1L + n * XSB + k * 2) = l;
    }
    for (int idx = tid; idx < HH * HH; idx += 256) {     // w2 [64][64]
        int n = idx >> 6, k = idx & 63;
        float v = w2[idx];
        __nv_bfloat16 h = __float2bfloat16_rn(v);
        __nv_bfloat16 l = __float2bfloat16_rn(v - __bfloat162float(h));
        *(__nv_bfloat16*)(wp + OW2H + n * HSB + k * 2) = h;
        *(__nv_bfloat16*)(wp + OW2L + n * HSB + k * 2) = l;
    }
    for (int idx = tid; idx < H * HH; idx += 256) {      // w3 [128][64]
        int n = idx >> 6, k = idx & 63;
        float v = w3[idx];
        __nv_bfloat16 h = __float2bfloat16_rn(v);
        __nv_bfloat16 l = __float2bfloat16_rn(v - __bfloat162float(h));
        *(__nv_bfloat16*)(wp + OW3H + n * HSB + k * 2) = h;
        *(__nv_bfloat16*)(wp + OW3L + n * HSB + k * 2) = l;
    }
    if (tid < HH) {
        ((float*)(wp + OB1))[tid] = b1[tid];
        ((float*)(wp + OB2))[tid] = b2[tid];
    }
    if (tid < H) ((float*)(wp + OB3))[tid] = b3[tid];
    __syncthreads();

    const float* b1s = (const float*)(wp + OB1);
    const float* b2s = (const float*)(wp + OB2);
    const float* b3s = (const float*)(wp + OB3);

    const int m0 = wid * 16;
    const int g  = lane >> 2;        // 0..7
    const int t  = lane & 3;         // 0..3

    // B-frag ldmatrix lane addressing
    const int b_row = (lane & 7) + ((lane >> 4) << 3);
    const int b_kof = ((lane >> 3) & 1) * 16;
    const uint32_t bw1h = sb + OW1H + b_row * XSB + b_kof;
    const uint32_t bw1l = sb + OW1L + b_row * XSB + b_kof;
    const uint32_t bw2h = sb + OW2H + b_row * HSB + b_kof;
    const uint32_t bw2l = sb + OW2L + b_row * HSB + b_kof;
    const uint32_t bw3h = sb + OW3H + b_row * HSB + b_kof;
    const uint32_t bw3l = sb + OW3L + b_row * HSB + b_kof;

    const int nr = (cnt_dev != nullptr) ? *cnt_dev : nrows;
    const int ntiles = (nr + TM - 1) / TM;

    for (int tile = blockIdx.x; tile < ntiles; tile += gridDim.x) {
        const int row0  = tile * TM;
        const int rowg_l  = row0 + m0 + g;
        const int rowg8_l = rowg_l + 8;
        const bool okg  = rowg_l  < nr;
        const bool okg8 = rowg8_l < nr;
        const int rowg  = (rowidx != nullptr) ? (okg  ? rowidx[rowg_l]  : 0) : rowg_l;
        const int rowg8 = (rowidx != nullptr) ? (okg8 ? rowidx[rowg8_l] : 0) : rowg8_l;

        float sg = 1.f, sg8 = 1.f;
        if (deg != nullptr) {
            if (okg)  sg  = 1.f / (float)max(deg[rowg],  1);
            if (okg8) sg8 = 1.f / (float)max(deg[rowg8], 1);
        }
        const float* rp  = in + (size_t)rowg  * H + 2 * t;
        const float* rp8 = in + (size_t)rowg8 * H + 2 * t;

        // ================= layer 1: K=128, N=64 =================
        float acc[8][4] = {};
        #pragma unroll
        for (int kt = 0; kt < 8; kt++) {
            // A frags direct from gmem (t-lanes cover one 32B sector)
            float2 p0 = okg  ? *(const float2*)(rp  + kt * 16)     : make_float2(0.f, 0.f);
            float2 p1 = okg8 ? *(const float2*)(rp8 + kt * 16)     : make_float2(0.f, 0.f);
            float2 p2 = okg  ? *(const float2*)(rp  + kt * 16 + 8) : make_float2(0.f, 0.f);
            float2 p3 = okg8 ? *(const float2*)(rp8 + kt * 16 + 8) : make_float2(0.f, 0.f);
            uint32_t ah[4], al[4];
            split2(p0.x * sg,  p0.y * sg,  ah[0], al[0]);
            split2(p1.x * sg8, p1.y * sg8, ah[1], al[1]);
            split2(p2.x * sg,  p2.y * sg,  ah[2], al[2]);
            split2(p3.x * sg8, p3.y * sg8, ah[3], al[3]);

            uint32_t bh[4][4], bl[4][4];
            #pragma unroll
            for (int np = 0; np < 4; np++) {
                ldm_x4(bw1h + np * 16 * XSB + kt * 32, bh[np]);
                ldm_x4(bw1l + np * 16 * XSB + kt * 32, bl[np]);
            }
            sweep(acc, ah, bh);
            sweep(acc, al, bh);
            sweep(acc, ah, bl);
        }

        // epi 1 -> layer-2 A frags (registers)
        uint32_t a2h[4][4], a2l[4][4];
        epi_frag(acc, b1s, t, a2h, a2l);

        // ================= layer 2: K=64, N=64 =================
        float acc2[8][4] = {};
        #pragma unroll
        for (int kt = 0; kt < 4; kt++) {
            uint32_t bh[4][4], bl[4][4];
            #pragma unroll
            for (int np = 0; np < 4; np++) {
                ldm_x4(bw2h + np * 16 * HSB + kt * 32, bh[np]);
                ldm_x4(bw2l + np * 16 * HSB + kt * 32, bl[np]);
            }
            sweep(acc2, a2h[kt], bh);
            sweep(acc2, a2l[kt], bh);
            sweep(acc2, a2h[kt], bl);
        }

        // epi 2 -> layer-3 A frags
        uint32_t a3h[4][4], a3l[4][4];
        epi_frag(acc2, b2s, t, a3h, a3l);

        // ================= layer 3: K=64, N=128 (two halves) =================
        #pragma unroll
        for (int nh = 0; nh < 2; nh++) {
            float acc3[8][4] = {};
            #pragma unroll
            for (int kt = 0; kt < 4; kt++) {
                uint32_t bh[4][4], bl[4][4];
                #pragma unroll
                for (int np = 0; np < 4; np++) {
                    uint32_t boff = (nh * 64 + np * 16) * HSB + kt * 32;
                    ldm_x4(bw3h + boff, bh[np]);
                    ldm_x4(bw3l + boff, bl[np]);
                }
                sweep(acc3, a3h[kt], bh);
                sweep(acc3, a3l[kt], bh);
                sweep(acc3, a3h[kt], bl);
            }
            #pragma unroll
            for (int nt = 0; nt < 8; nt++) {
                int col = nh * 64 + nt * 8 + 2 * t;
                float bx = b3s[col], by = b3s[col + 1];
                if (okg) {
                    float2 v = make_float2(acc3[nt][0] + bx, acc3[nt][1] + by);
                    *reinterpret_cast<float2*>(out + (size_t)rowg * H + col) = v;
                }
                if (okg8) {
                    float2 v = make_float2(acc3[nt][2] + bx, acc3[nt][3] + by);
                    *reinterpret_cast<float2*>(out + (size_t)rowg8 * H + col) = v;
                }
            }
        }
    }
}

// ---------------------------------------------------------------------------
extern "C" void kernel_launch(void* const* d_in, const int* in_sizes, int n_in,
                              void* d_out, int out_size) {
    const float* feat   = (const float*)d_in[0];
    const int*   src    = (const int*)d_in[1];
    const int*   dst    = (const int*)d_in[2];
    const int*   r      = (const int*)d_in[3];
    const int*   inv    = (const int*)d_in[4];
    const float* inv_w1 = (const float*)d_in[5];
    const float* inv_b1 = (const float*)d_in[6];
    const float* inv_w2 = (const float*)d_in[7];
    const float* inv_b2 = (const float*)d_in[8];
    const float* inv_w3 = (const float*)d_in[9];
    const float* inv_b3 = (const float*)d_in[10];
    const float* and_w1 = (const float*)d_in[11];
    const float* and_b1 = (const float*)d_in[12];
    const float* and_w2 = (const float*)d_in[13];
    const float* and_b2 = (const float*)d_in[14];
    const float* and_w3 = (const float*)d_in[15];
    const float* and_b3 = (const float*)d_in[16];

    const int n = in_sizes[0] / H;
    const int e = in_sizes[1];

    float *invfeat, *nsum, *res;
    int *deg, *idxl, *cnt;
    cudaGetSymbolAddress((void**)&invfeat, g_invfeat);
    cudaGetSymbolAddress((void**)&nsum,    g_nsum);
    cudaGetSymbolAddress((void**)&res,     g_res);
    cudaGetSymbolAddress((void**)&deg,     g_deg);
    cudaGetSymbolAddress((void**)&idxl,    g_idx);
    cudaGetSymbolAddress((void**)&cnt,     g_cnt);

    cudaFuncSetAttribute(mlp3_mma, cudaFuncAttributeMaxDynamicSharedMemorySize, SMEM_BYTES);

    // 1. zero accumulators + compaction counter
    int zgrid = (n * (H / 4) + 255) / 256;
    zero_kernel<<<zgrid, 256>>>(n);

    const int ntiles = (n + TM - 1) / TM;
    const int mgrid  = ntiles < 296 ? ntiles : 296;   // 2 CTAs/SM

    // 2. inv_feat = mlp3_inv(feat)
    mlp3_mma<<<mgrid, 256, SMEM_BYTES>>>(
        feat, invfeat, inv_w1, inv_b1, inv_w2, inv_b2, inv_w3, inv_b3,
        nullptr, nullptr, nullptr, n);

    // 3. edge gather + atomic scatter
    long long sthreads = (long long)e * 32;
    int sgrid = (int)((sthreads + 255) / 256);
    scatter_kernel<<<sgrid, 256>>>(feat, src, dst, r, e);

    // 4. res = mlp3_and(nsum / max(deg,1))
    mlp3_mma<<<mgrid, 256, SMEM_BYTES>>>(
        nsum, res, and_w1, and_b1, and_w2, and_b2, and_w3, and_b3,
        deg, nullptr, nullptr, n);

    // 5a. compact inv==1 rows; copy inv==0 rows res->out
    compact_kernel<<<1024, 256>>>(inv, res, (float*)d_out, n);

    // 5b. out[idx] = mlp3_inv(res[idx]) for compacted rows
    mlp3_mma<<<296, 256, SMEM_BYTES>>>(
        res, (float*)d_out, inv_w1, inv_b1, inv_w2, inv_b2, inv_w3, inv_b3,
        nullptr, idxl, cnt, n);
}